// round 1
// baseline (speedup 1.0000x reference)
#include <cuda_runtime.h>
#include <cuda_bf16.h>

// Shapes are fixed by the problem.
#define BSZ   64
#define CC    256
#define HWN   3136
#define TT    6
#define DD    192
#define NHH   4
#define DHH   64
#define SLABS 7
#define SLABN 448      // HWN / SLABS
#define TN    32       // n-tile
#define NTILES 14      // SLABN / TN
#define FST   36       // f smem row stride (16B-aligned float4 rows, conflict-free)
#define EST   36

// Scratch (static device arrays; no runtime allocation)
__device__ float g_qs[TT*BSZ*CC];     // q * scale, bias included
__device__ float g_gate[TT*BSZ*CC];   // h_sigmoid(alpha)*2
__device__ float g_accP[BSZ*SLABS*TT*CC];   // unnormalized attn_out partials
__device__ float g_maccP[BSZ*SLABS*TT*CC];  // mlp partials
__device__ float g_Lp[BSZ*SLABS*24];        // exp-sum partials

// ---------------------------------------------------------------------------
// Kernel 1: q = (tokens @ q_w^T + q_b) * dh^-0.5 ; gate = hsig(alpha)+...
// grid: (BSZ), 256 threads. Weights stay L2-resident across blocks.
// ---------------------------------------------------------------------------
__global__ void __launch_bounds__(256) prep_kernel(
    const float* __restrict__ tokens,
    const float* __restrict__ q_w,  const float* __restrict__ q_b,
    const float* __restrict__ a_w,  const float* __restrict__ a_b)
{
    __shared__ float tok_s[TT*DD];
    int b = blockIdx.x, tid = threadIdx.x;
    for (int i = tid; i < TT*DD; i += 256) {
        int t = i / DD, d = i % DD;
        tok_s[i] = tokens[(t*BSZ + b)*DD + d];
    }
    __syncthreads();
    int w = tid >> 5, lane = tid & 31;
    for (int cc = 0; cc < 32; cc++) {
        int c = w*32 + cc;
        float qp[TT], ap[TT];
        #pragma unroll
        for (int t = 0; t < TT; t++) { qp[t] = 0.f; ap[t] = 0.f; }
        #pragma unroll
        for (int j = 0; j < 6; j++) {
            int d = lane + 32*j;
            float wq = q_w[c*DD + d];
            float wa = a_w[c*DD + d];
            #pragma unroll
            for (int t = 0; t < TT; t++) {
                float tv = tok_s[t*DD + d];
                qp[t] += wq * tv;
                ap[t] += wa * tv;
            }
        }
        #pragma unroll
        for (int t = 0; t < TT; t++) {
            #pragma unroll
            for (int o = 16; o; o >>= 1) {
                qp[t] += __shfl_xor_sync(0xffffffffu, qp[t], o);
                ap[t] += __shfl_xor_sync(0xffffffffu, ap[t], o);
            }
        }
        if (lane == 0) {
            #pragma unroll
            for (int t = 0; t < TT; t++) {
                g_qs[(t*BSZ + b)*CC + c] = (qp[t] + q_b[c]) * 0.125f;
                float al = ap[t] + a_b[c] + 3.0f;
                al = fminf(fmaxf(al, 0.0f), 6.0f) * (1.0f/3.0f);  // /6 * 2
                g_gate[(t*BSZ + b)*CC + c] = al;
            }
        }
    }
}

// ---------------------------------------------------------------------------
// Kernel 2: fused single pass over features.
//   per n: logits s[h,t] (written to attn output), e = exp(s), L += e,
//          acc[t,c] += e[h(c),t]*f[c,n], macc[t,c] += mlp_w[t,n]*f[c,n]
// grid: (SLABS, BSZ), 256 threads, 57 KB dynamic smem.
// ---------------------------------------------------------------------------
__global__ void __launch_bounds__(256) main_kernel(
    const float* __restrict__ feat,
    const float* __restrict__ mlp_w,
    float* __restrict__ attn_out)
{
    extern __shared__ float sm[];
    float* fs  = sm;                 // CC*FST  = 9216 floats
    float* es  = fs + CC*FST;        // 24*EST  = 864
    float* qs  = es + 24*EST;        // TT*CC   = 1536
    float* mws = qs + TT*CC;         // TT*SLABN= 2688

    int slab = blockIdx.x, b = blockIdx.y;
    int tid = threadIdx.x;

    #pragma unroll
    for (int t = 0; t < TT; t++) qs[t*CC + tid] = g_qs[(t*BSZ + b)*CC + tid];
    for (int i = tid; i < TT*SLABN; i += 256) {
        int t = i / SLABN, j = i % SLABN;
        mws[i] = mlp_w[t*HWN + slab*SLABN + j];
    }

    float acc[TT], macc[TT], Lacc[TT];
    #pragma unroll
    for (int t = 0; t < TT; t++) { acc[t]=0.f; macc[t]=0.f; Lacc[t]=0.f; }

    const float* fb = feat + (size_t)b * CC * HWN;
    int h1 = (tid >> 5) & 3, nl = tid & 31;   // phase-1 ids (tid < 128)
    int h2 = tid >> 6;                        // phase-2 head of c = tid

    for (int tile = 0; tile < NTILES; tile++) {
        int n0 = slab*SLABN + tile*TN;
        __syncthreads();  // previous phase 2 done with fs/es
        // ---- stage f[b, :, n0:n0+32] into smem (float4, coalesced) ----
        #pragma unroll
        for (int it = 0; it < 8; it++) {
            int c = it*32 + (tid >> 3);
            int nq = (tid & 7) * 4;
            float4 v = *reinterpret_cast<const float4*>(fb + c*HWN + n0 + nq);
            *reinterpret_cast<float4*>(fs + c*FST + nq) = v;
        }
        __syncthreads();
        // ---- phase 1: logits + exp (warps 0..3, warp == head) ----
        if (tid < 128) {
            float s[TT];
            #pragma unroll
            for (int t = 0; t < TT; t++) s[t] = 0.f;
            #pragma unroll
            for (int d4 = 0; d4 < 16; d4++) {
                float f0 = fs[(h1*DHH + d4*4 + 0)*FST + nl];
                float f1 = fs[(h1*DHH + d4*4 + 1)*FST + nl];
                float f2 = fs[(h1*DHH + d4*4 + 2)*FST + nl];
                float f3 = fs[(h1*DHH + d4*4 + 3)*FST + nl];
                #pragma unroll
                for (int t = 0; t < TT; t++) {
                    const float4 q = *reinterpret_cast<const float4*>(qs + t*CC + h1*DHH + d4*4);
                    s[t] += q.x*f0; s[t] += q.y*f1; s[t] += q.z*f2; s[t] += q.w*f3;
                }
            }
            size_t gb = ((size_t)(b*NHH + h1) * TT) * HWN;
            #pragma unroll
            for (int t = 0; t < TT; t++) {
                attn_out[gb + (size_t)t*HWN + n0 + nl] = s[t];
                float ev = __expf(s[t]);     // logits are O(0.3): no max-sub needed
                es[(h1*TT + t)*EST + nl] = ev;
                Lacc[t] += ev;
            }
        }
        __syncthreads();
        // ---- phase 2: register-resident rank-1 accumulation (all 256) ----
        {
            float fr[TN];
            #pragma unroll
            for (int k = 0; k < 8; k++) {
                float4 v = *reinterpret_cast<const float4*>(fs + tid*FST + k*4);
                fr[k*4+0]=v.x; fr[k*4+1]=v.y; fr[k*4+2]=v.z; fr[k*4+3]=v.w;
            }
            #pragma unroll
            for (int t = 0; t < TT; t++) {
                const float* erow = es + (h2*TT + t)*EST;
                const float* mrow = mws + t*SLABN + tile*TN;
                float a = acc[t], m = macc[t];
                #pragma unroll
                for (int k = 0; k < 8; k++) {
                    float4 e4 = *reinterpret_cast<const float4*>(erow + k*4);
                    float4 m4 = *reinterpret_cast<const float4*>(mrow + k*4);
                    a += e4.x*fr[k*4+0]; m += m4.x*fr[k*4+0];
                    a += e4.y*fr[k*4+1]; m += m4.y*fr[k*4+1];
                    a += e4.z*fr[k*4+2]; m += m4.z*fr[k*4+2];
                    a += e4.w*fr[k*4+3]; m += m4.w*fr[k*4+3];
                }
                acc[t] = a; macc[t] = m;
            }
        }
    }

    // ---- write per-slab partials (deterministic; reduced in epi) ----
    #pragma unroll
    for (int t = 0; t < TT; t++) {
        g_accP [((b*SLABS + slab)*TT + t)*CC + tid] = acc[t];
        g_maccP[((b*SLABS + slab)*TT + t)*CC + tid] = macc[t];
    }
    if (tid < 128) {
        #pragma unroll
        for (int t = 0; t < TT; t++) {
            float v = Lacc[t];
            #pragma unroll
            for (int o = 16; o; o >>= 1) v += __shfl_xor_sync(0xffffffffu, v, o);
            if (nl == 0) g_Lp[(b*SLABS + slab)*24 + h1*TT + t] = v;
        }
    }
}

// ---------------------------------------------------------------------------
// Kernel 3: slab reduce + /L + gate + proj + residual + LayerNorm.
// grid: (BSZ), 256 threads, proj_w cached in 192 KB smem.
// ---------------------------------------------------------------------------
__global__ void __launch_bounds__(256) epi_kernel(
    const float* __restrict__ tokens, const float* __restrict__ mlp_b,
    const float* __restrict__ proj_w, const float* __restrict__ proj_b,
    const float* __restrict__ ln_g,   const float* __restrict__ ln_b,
    float* __restrict__ out_tok)
{
    extern __shared__ float sm[];
    float* pw   = sm;              // DD*CC = 49152
    float* ts   = pw + DD*CC;      // 256
    float* tv   = ts + CC;         // 192
    float* Linv = tv + DD;         // 24
    float* red  = Linv + 24;       // 16

    int b = blockIdx.x, tid = threadIdx.x;
    for (int i = tid; i < DD*CC; i += 256) pw[i] = proj_w[i];
    if (tid < 24) {
        float L = 0.f;
        #pragma unroll
        for (int s = 0; s < SLABS; s++) L += g_Lp[(b*SLABS + s)*24 + tid];
        Linv[tid] = 1.0f / L;
    }
    __syncthreads();
    int w = tid >> 5, lane = tid & 31;

    for (int t = 0; t < TT; t++) {
        float a = 0.f, m = 0.f;
        #pragma unroll
        for (int s = 0; s < SLABS; s++) {
            a += g_accP [((b*SLABS + s)*TT + t)*CC + tid];
            m += g_maccP[((b*SLABS + s)*TT + t)*CC + tid];
        }
        float v = (m + mlp_b[t] + a * Linv[(tid >> 6)*TT + t])
                  * g_gate[(t*BSZ + b)*CC + tid];
        ts[tid] = v;
        __syncthreads();
        // proj: warp per 24 d rows, lanes over c (float4)
        #pragma unroll
        for (int dd = 0; dd < 24; dd++) {
            int d = w*24 + dd;
            const float4* prow = reinterpret_cast<const float4*>(pw + d*CC);
            const float4* tsr  = reinterpret_cast<const float4*>(ts);
            float4 p0 = prow[lane],      t0 = tsr[lane];
            float4 p1 = prow[lane + 32], t1 = tsr[lane + 32];
            float sum = p0.x*t0.x + p0.y*t0.y + p0.z*t0.z + p0.w*t0.w
                      + p1.x*t1.x + p1.y*t1.y + p1.z*t1.z + p1.w*t1.w;
            #pragma unroll
            for (int o = 16; o; o >>= 1) sum += __shfl_xor_sync(0xffffffffu, sum, o);
            if (lane == 0) tv[d] = sum + proj_b[d] + tokens[(t*BSZ + b)*DD + d];
        }
        __syncthreads();
        // LayerNorm over DD=192
        float x  = (tid < DD) ? tv[tid] : 0.0f;
        float x2 = x * x;
        #pragma unroll
        for (int o = 16; o; o >>= 1) {
            x  += __shfl_xor_sync(0xffffffffu, x,  o);
            x2 += __shfl_xor_sync(0xffffffffu, x2, o);
        }
        if (lane == 0) { red[w] = x; red[8 + w] = x2; }
        __syncthreads();
        float sA = red[0]+red[1]+red[2]+red[3]+red[4]+red[5]+red[6]+red[7];
        float sB = red[8]+red[9]+red[10]+red[11]+red[12]+red[13]+red[14]+red[15];
        float mu = sA / (float)DD;
        float var = sB / (float)DD - mu*mu;
        float rstd = rsqrtf(var + 1e-5f);
        if (tid < DD) {
            out_tok[((size_t)t*BSZ + b)*DD + tid] =
                (tv[tid] - mu) * rstd * ln_g[tid] + ln_b[tid];
        }
        __syncthreads();  // before ts/tv reuse
    }
}

// ---------------------------------------------------------------------------
extern "C" void kernel_launch(void* const* d_in, const int* in_sizes, int n_in,
                              void* d_out, int out_size)
{
    const float* feat    = (const float*)d_in[0];
    const float* tokens  = (const float*)d_in[1];
    const float* mlp_w   = (const float*)d_in[2];
    const float* mlp_b   = (const float*)d_in[3];
    const float* q_w     = (const float*)d_in[4];
    const float* q_b     = (const float*)d_in[5];
    const float* alpha_w = (const float*)d_in[6];
    const float* alpha_b = (const float*)d_in[7];
    const float* proj_w  = (const float*)d_in[8];
    const float* proj_b  = (const float*)d_in[9];
    const float* ln_g    = (const float*)d_in[10];
    const float* ln_b    = (const float*)d_in[11];

    float* out      = (float*)d_out;
    float* out_tok  = out;                      // [T, bs, D]
    float* out_attn = out + (size_t)TT*BSZ*DD;  // [bs, h, T, HW]

    size_t smB = (size_t)(CC*FST + 24*EST + TT*CC + TT*SLABN) * sizeof(float);
    size_t smC = (size_t)(DD*CC + CC + DD + 24 + 16) * sizeof(float);
    cudaFuncSetAttribute(main_kernel, cudaFuncAttributeMaxDynamicSharedMemorySize, (int)smB);
    cudaFuncSetAttribute(epi_kernel,  cudaFuncAttributeMaxDynamicSharedMemorySize, (int)smC);

    prep_kernel<<<BSZ, 256>>>(tokens, q_w, q_b, alpha_w, alpha_b);
    main_kernel<<<dim3(SLABS, BSZ), 256, smB>>>(feat, mlp_w, out_attn);
    epi_kernel<<<BSZ, 256, smC>>>(tokens, mlp_b, proj_w, proj_b, ln_g, ln_b, out_tok);
}

// round 2
// speedup vs baseline: 1.2864x; 1.2864x over previous
#include <cuda_runtime.h>
#include <cuda_bf16.h>

#define BSZ   64
#define CC    256
#define HWN   3136
#define TT    6
#define DD    192
#define NHH   4
#define DHH   64
#define NBLK  592         // 148 SMs * 4 : perfectly balanced
#define NTILE 6272        // 64 b * 98 tiles (TN=32)
#define TPB   98          // tiles per batch
#define TN    32
#define FST   36          // fs row stride (floats)
#define EST2  34          // es2/mws2 row stride (float2 units)

typedef unsigned long long ull;

__device__ __forceinline__ ull pk2(float lo, float hi) {
    ull r; asm("mov.b64 %0,{%1,%2};" : "=l"(r) : "f"(lo), "f"(hi)); return r;
}
__device__ __forceinline__ float2 upk2(ull v) {
    float2 f; asm("mov.b64 {%0,%1},%2;" : "=f"(f.x), "=f"(f.y) : "l"(v)); return f;
}
__device__ __forceinline__ ull f2fma(ull a, ull b, ull c) {
    ull d; asm("fma.rn.f32x2 %0,%1,%2,%3;" : "=l"(d) : "l"(a), "l"(b), "l"(c)); return d;
}
__device__ __forceinline__ ull f2add(ull a, ull b) {
    ull d; asm("add.rn.f32x2 %0,%1,%2;" : "=l"(d) : "l"(a), "l"(b)); return d;
}

__device__ __forceinline__ int sfun(int blk) { return (blk * 392) / 37; }  // 6272/592

// Scratch
__device__ float g_qs2[TT*BSZ*CC];           // packed t-pairs: [(t2*64+b)*256+c]*2
__device__ float g_gate[TT*BSZ*CC];
__device__ float g_accP[NBLK*2*TT*CC];
__device__ float g_maccP[NBLK*2*TT*CC];
__device__ float g_Lp[NBLK*2*24];

// ---------------------------------------------------------------------------
// prep: q = (tok@q_w^T + q_b)*0.125 (packed t-pairs), gate = hsig(alpha)*2
// grid (4 c-quarters, 64 b), 256 threads: thread = (c_loc = tid>>2, dq = tid&3)
// d chunks interleaved at float4 granularity for full-sector LDG.
// ---------------------------------------------------------------------------
__global__ void __launch_bounds__(256) prep_kernel(
    const float* __restrict__ tokens,
    const float* __restrict__ q_w,  const float* __restrict__ q_b,
    const float* __restrict__ a_w,  const float* __restrict__ a_b)
{
    __shared__ float tok_t[DD*8];            // [d][t0..t5,pad,pad]
    __shared__ float part[3*64*12];
    int cq = blockIdx.x, b = blockIdx.y, tid = threadIdx.x;

    for (int i = tid; i < TT*DD; i += 256) {
        int t = i / DD, d = i % DD;
        tok_t[d*8 + t] = tokens[(t*BSZ + b)*DD + d];
    }
    __syncthreads();

    int c_loc = tid >> 2, dq = tid & 3;
    int c = cq*64 + c_loc;
    float qp[TT], ap[TT];
    #pragma unroll
    for (int t = 0; t < TT; t++) { qp[t] = 0.f; ap[t] = 0.f; }

    #pragma unroll 4
    for (int j = 0; j < 12; j++) {
        int d0 = j*16 + dq*4;
        float4 q4 = *reinterpret_cast<const float4*>(q_w + c*DD + d0);
        float4 a4 = *reinterpret_cast<const float4*>(a_w + c*DD + d0);
        float qv[4] = {q4.x, q4.y, q4.z, q4.w};
        float av[4] = {a4.x, a4.y, a4.z, a4.w};
        #pragma unroll
        for (int dd = 0; dd < 4; dd++) {
            float4 tA = *reinterpret_cast<const float4*>(tok_t + (d0+dd)*8);
            float4 tB = *reinterpret_cast<const float4*>(tok_t + (d0+dd)*8 + 4);
            float tv[6] = {tA.x, tA.y, tA.z, tA.w, tB.x, tB.y};
            #pragma unroll
            for (int t = 0; t < TT; t++) {
                qp[t] += qv[dd] * tv[t];
                ap[t] += av[dd] * tv[t];
            }
        }
    }
    if (dq != 0) {
        float* p = part + (dq-1)*64*12 + c_loc*12;
        #pragma unroll
        for (int t = 0; t < TT; t++) { p[t] = qp[t]; p[6+t] = ap[t]; }
    }
    __syncthreads();
    if (dq == 0) {
        #pragma unroll
        for (int r = 0; r < 3; r++) {
            const float* p = part + r*64*12 + c_loc*12;
            #pragma unroll
            for (int t = 0; t < TT; t++) { qp[t] += p[t]; ap[t] += p[6+t]; }
        }
        float qb = q_b[c], ab = a_b[c];
        #pragma unroll
        for (int t2 = 0; t2 < 3; t2++) {
            float q0 = (qp[2*t2]   + qb) * 0.125f;
            float q1 = (qp[2*t2+1] + qb) * 0.125f;
            reinterpret_cast<float2*>(g_qs2)[(t2*BSZ + b)*CC + c] = make_float2(q0, q1);
        }
        #pragma unroll
        for (int t = 0; t < TT; t++) {
            float al = ap[t] + ab + 3.0f;
            al = fminf(fmaxf(al, 0.0f), 6.0f) * (1.0f/3.0f);
            g_gate[(t*BSZ + b)*CC + c] = al;
        }
    }
}

// ---------------------------------------------------------------------------
// main: balanced persistent-range fused pass. 592 blocks, 256 threads.
// ---------------------------------------------------------------------------
__global__ void __launch_bounds__(256) main_kernel(
    const float* __restrict__ feat,
    const float* __restrict__ mlp_w,
    float* __restrict__ attn_out)
{
    extern __shared__ float sm[];
    float* fs   = sm;                        // 256*36 = 9216
    ull*   es2  = (ull*)(sm + 9216);         // 12*34 ull = 816 floats
    ull*   qs2  = (ull*)(sm + 10032);        // 3*256 ull = 1536 floats
    ull*   mws2 = (ull*)(sm + 11568);        // 3*34 ull  = 204 floats

    int blk = blockIdx.x, tid = threadIdx.x;
    int h1 = (tid >> 5) & 3, nl = tid & 31;
    int h2 = tid >> 6;
    int s = sfun(blk), e = sfun(blk + 1);

    ull acc2[3] = {0,0,0}, macc2[3] = {0,0,0}, Lacc2[3] = {0,0,0};
    int curb = -1, seg = 0;

    for (int tau = s; tau < e; tau++) {
        int b = tau / TPB;
        int n0 = (tau - b*TPB) * TN;
        bool newb = (b != curb);
        if (newb) {
            if (curb >= 0) {
                int idx = blk*2 + seg;
                #pragma unroll
                for (int t2 = 0; t2 < 3; t2++) {
                    float2 ua = upk2(acc2[t2]),  um = upk2(macc2[t2]);
                    g_accP [idx*1536 + (2*t2  )*CC + tid] = ua.x;
                    g_accP [idx*1536 + (2*t2+1)*CC + tid] = ua.y;
                    g_maccP[idx*1536 + (2*t2  )*CC + tid] = um.x;
                    g_maccP[idx*1536 + (2*t2+1)*CC + tid] = um.y;
                    acc2[t2] = 0; macc2[t2] = 0;
                }
                if (tid < 128) {
                    float lv[TT];
                    #pragma unroll
                    for (int t2 = 0; t2 < 3; t2++) {
                        float2 u = upk2(Lacc2[t2]); lv[2*t2] = u.x; lv[2*t2+1] = u.y;
                        Lacc2[t2] = 0;
                    }
                    #pragma unroll
                    for (int t = 0; t < TT; t++) {
                        #pragma unroll
                        for (int o = 16; o; o >>= 1)
                            lv[t] += __shfl_xor_sync(0xffffffffu, lv[t], o);
                    }
                    if (nl == 0) {
                        #pragma unroll
                        for (int t = 0; t < TT; t++)
                            g_Lp[idx*24 + h1*TT + t] = lv[t];
                    }
                }
                seg++;
            }
            curb = b;
        }

        __syncthreads();
        // ---- stage ----
        const float* fb = feat + (size_t)b * CC * HWN + n0;
        #pragma unroll
        for (int it = 0; it < 8; it++) {
            int c = it*32 + (tid >> 3);
            int nq = (tid & 7) * 4;
            float4 v = *reinterpret_cast<const float4*>(fb + (size_t)c*HWN + nq);
            *reinterpret_cast<float4*>(fs + c*FST + nq) = v;
        }
        if (tid < 96) {
            int t2 = tid >> 5, n = tid & 31;
            float m0 = mlp_w[(2*t2  )*HWN + n0 + n];
            float m1 = mlp_w[(2*t2+1)*HWN + n0 + n];
            mws2[t2*EST2 + n] = pk2(m0, m1);
        }
        if (newb) {
            #pragma unroll
            for (int t2 = 0; t2 < 3; t2++) {
                float2 q2 = reinterpret_cast<const float2*>(g_qs2)[(t2*BSZ + b)*CC + tid];
                qs2[t2*CC + tid] = pk2(q2.x, q2.y);
            }
        }
        __syncthreads();

        // ---- phase 1: logits + exp (warps 0..3, warp = head) ----
        if (tid < 128) {
            ull s2[3] = {0,0,0};
            const float* fsr = fs + (h1*DHH)*FST + nl;
            const ull* qb = qs2 + h1*DHH;
            #pragma unroll
            for (int d = 0; d < DHH; d += 2) {
                float f0 = fsr[d*FST];
                float f1 = fsr[d*FST + FST];
                ull ff0 = pk2(f0, f0), ff1 = pk2(f1, f1);
                #pragma unroll
                for (int t2 = 0; t2 < 3; t2++) {
                    ulonglong2 q = *reinterpret_cast<const ulonglong2*>(qb + t2*CC + d);
                    s2[t2] = f2fma(q.x, ff0, s2[t2]);
                    s2[t2] = f2fma(q.y, ff1, s2[t2]);
                }
            }
            size_t gb = ((size_t)(b*NHH + h1) * TT) * HWN + n0 + nl;
            #pragma unroll
            for (int t2 = 0; t2 < 3; t2++) {
                float2 sv = upk2(s2[t2]);
                attn_out[gb + (size_t)(2*t2  )*HWN] = sv.x;
                attn_out[gb + (size_t)(2*t2+1)*HWN] = sv.y;
                float e0 = __expf(sv.x), e1 = __expf(sv.y);   // logits O(0.3): safe
                ull ee = pk2(e0, e1);
                es2[(h1*3 + t2)*EST2 + nl] = ee;
                Lacc2[t2] = f2add(Lacc2[t2], ee);
            }
        }
        __syncthreads();

        // ---- phase 2: packed rank-1 accumulation (all 256 threads) ----
        {
            const float* fr = fs + tid*FST;
            const ull* er = es2 + (h2*3)*EST2;
            #pragma unroll
            for (int n = 0; n < TN; n += 4) {
                float4 f4 = *reinterpret_cast<const float4*>(fr + n);
                ull fa = pk2(f4.x, f4.x), fb2 = pk2(f4.y, f4.y);
                ull fc = pk2(f4.z, f4.z), fd  = pk2(f4.w, f4.w);
                #pragma unroll
                for (int t2 = 0; t2 < 3; t2++) {
                    ulonglong2 eA = *reinterpret_cast<const ulonglong2*>(er + t2*EST2 + n);
                    ulonglong2 eB = *reinterpret_cast<const ulonglong2*>(er + t2*EST2 + n + 2);
                    ulonglong2 mA = *reinterpret_cast<const ulonglong2*>(mws2 + t2*EST2 + n);
                    ulonglong2 mB = *reinterpret_cast<const ulonglong2*>(mws2 + t2*EST2 + n + 2);
                    acc2[t2]  = f2fma(eA.x, fa,  acc2[t2]);
                    acc2[t2]  = f2fma(eA.y, fb2, acc2[t2]);
                    acc2[t2]  = f2fma(eB.x, fc,  acc2[t2]);
                    acc2[t2]  = f2fma(eB.y, fd,  acc2[t2]);
                    macc2[t2] = f2fma(mA.x, fa,  macc2[t2]);
                    macc2[t2] = f2fma(mA.y, fb2, macc2[t2]);
                    macc2[t2] = f2fma(mB.x, fc,  macc2[t2]);
                    macc2[t2] = f2fma(mB.y, fd,  macc2[t2]);
                }
            }
        }
    }

    // final flush
    {
        int idx = blk*2 + seg;
        #pragma unroll
        for (int t2 = 0; t2 < 3; t2++) {
            float2 ua = upk2(acc2[t2]), um = upk2(macc2[t2]);
            g_accP [idx*1536 + (2*t2  )*CC + tid] = ua.x;
            g_accP [idx*1536 + (2*t2+1)*CC + tid] = ua.y;
            g_maccP[idx*1536 + (2*t2  )*CC + tid] = um.x;
            g_maccP[idx*1536 + (2*t2+1)*CC + tid] = um.y;
        }
        if (tid < 128) {
            float lv[TT];
            #pragma unroll
            for (int t2 = 0; t2 < 3; t2++) {
                float2 u = upk2(Lacc2[t2]); lv[2*t2] = u.x; lv[2*t2+1] = u.y;
            }
            #pragma unroll
            for (int t = 0; t < TT; t++) {
                #pragma unroll
                for (int o = 16; o; o >>= 1)
                    lv[t] += __shfl_xor_sync(0xffffffffu, lv[t], o);
            }
            if (nl == 0) {
                #pragma unroll
                for (int t = 0; t < TT; t++)
                    g_Lp[idx*24 + h1*TT + t] = lv[t];
            }
        }
    }
}

// ---------------------------------------------------------------------------
// epi: grid (64, 6) = (b, t). partial reduce + gate + proj + residual + LN.
// ---------------------------------------------------------------------------
__global__ void __launch_bounds__(256) epi_kernel(
    const float* __restrict__ tokens, const float* __restrict__ mlp_b,
    const float* __restrict__ proj_w, const float* __restrict__ proj_b,
    const float* __restrict__ ln_g,   const float* __restrict__ ln_b,
    float* __restrict__ out_tok)
{
    __shared__ float ts[CC];
    __shared__ float tv[DD];
    __shared__ float red[16];
    int b = blockIdx.x, t = blockIdx.y, tid = threadIdx.x;
    int w = tid >> 5, lane = tid & 31, h = tid >> 6;

    // find contributing blocks for this b
    float a = 0.f, m = 0.f, L = 0.f;
    int g = (TPB*b*37) / 392;
    while (sfun(g) > TPB*b) g--;
    while (sfun(g+1) <= TPB*b) g++;
    int lim = TPB*b + TPB;
    for (int blk = g; blk < NBLK && sfun(blk) < lim; blk++) {
        int seg = b - sfun(blk)/TPB;        // 0 or 1
        int idx = blk*2 + seg;
        a += g_accP [idx*1536 + t*CC + tid];
        m += g_maccP[idx*1536 + t*CC + tid];
        L += g_Lp[idx*24 + h*TT + t];
    }
    float v = (m + mlp_b[t] + a * (1.0f / L)) * g_gate[(t*BSZ + b)*CC + tid];
    ts[tid] = v;
    __syncthreads();

    // proj: warp w handles 24 d rows; proj_w streamed from L2
    #pragma unroll 4
    for (int dd = 0; dd < 24; dd++) {
        int d = w*24 + dd;
        const float4* prow = reinterpret_cast<const float4*>(proj_w + d*CC);
        const float4* tsr  = reinterpret_cast<const float4*>(ts);
        float4 p0 = prow[lane],      t0 = tsr[lane];
        float4 p1 = prow[lane + 32], t1 = tsr[lane + 32];
        float sum = p0.x*t0.x + p0.y*t0.y + p0.z*t0.z + p0.w*t0.w
                  + p1.x*t1.x + p1.y*t1.y + p1.z*t1.z + p1.w*t1.w;
        #pragma unroll
        for (int o = 16; o; o >>= 1) sum += __shfl_xor_sync(0xffffffffu, sum, o);
        if (lane == 0) tv[d] = sum + proj_b[d] + tokens[(t*BSZ + b)*DD + d];
    }
    __syncthreads();

    float x  = (tid < DD) ? tv[tid] : 0.0f;
    float x2 = x * x;
    #pragma unroll
    for (int o = 16; o; o >>= 1) {
        x  += __shfl_xor_sync(0xffffffffu, x,  o);
        x2 += __shfl_xor_sync(0xffffffffu, x2, o);
    }
    if (lane == 0) { red[w] = x; red[8 + w] = x2; }
    __syncthreads();
    float sA = red[0]+red[1]+red[2]+red[3]+red[4]+red[5]+red[6]+red[7];
    float sB = red[8]+red[9]+red[10]+red[11]+red[12]+red[13]+red[14]+red[15];
    float mu = sA * (1.0f/DD);
    float var = sB * (1.0f/DD) - mu*mu;
    float rstd = rsqrtf(var + 1e-5f);
    if (tid < DD) {
        out_tok[((size_t)t*BSZ + b)*DD + tid] =
            (tv[tid] - mu) * rstd * ln_g[tid] + ln_b[tid];
    }
}

// ---------------------------------------------------------------------------
extern "C" void kernel_launch(void* const* d_in, const int* in_sizes, int n_in,
                              void* d_out, int out_size)
{
    const float* feat    = (const float*)d_in[0];
    const float* tokens  = (const float*)d_in[1];
    const float* mlp_w   = (const float*)d_in[2];
    const float* mlp_b   = (const float*)d_in[3];
    const float* q_w     = (const float*)d_in[4];
    const float* q_b     = (const float*)d_in[5];
    const float* alpha_w = (const float*)d_in[6];
    const float* alpha_b = (const float*)d_in[7];
    const float* proj_w  = (const float*)d_in[8];
    const float* proj_b  = (const float*)d_in[9];
    const float* ln_g    = (const float*)d_in[10];
    const float* ln_b    = (const float*)d_in[11];

    float* out      = (float*)d_out;
    float* out_tok  = out;                      // [T, bs, D]
    float* out_attn = out + (size_t)TT*BSZ*DD;  // [bs, h, T, HW]

    size_t smB = 11772 * sizeof(float);   // 47088 B

    prep_kernel<<<dim3(4, BSZ), 256>>>(tokens, q_w, q_b, alpha_w, alpha_b);
    main_kernel<<<NBLK, 256, smB>>>(feat, mlp_w, out_attn);
    epi_kernel<<<dim3(BSZ, TT), 256>>>(tokens, mlp_b, proj_w, proj_b,
                                       ln_g, ln_b, out_tok);
}

// round 3
// speedup vs baseline: 1.3680x; 1.0634x over previous
#include <cuda_runtime.h>
#include <cuda_bf16.h>

#define BSZ   64
#define CC    256
#define HWN   3136
#define TT    6
#define DD    192
#define NHH   4
#define DHH   64
#define NBLK  592         // 148 SMs * 4 resident blocks: one persistent wave
#define NTILE 6272        // 64 b * 98 tiles (TN=32)
#define TPB   98          // tiles per batch
#define TN    32
#define FST   36          // fs row stride (floats)
#define EST2  34          // es2/mws2 row stride (float2 units)

typedef unsigned long long ull;

__device__ __forceinline__ ull pk2(float lo, float hi) {
    ull r; asm("mov.b64 %0,{%1,%2};" : "=l"(r) : "f"(lo), "f"(hi)); return r;
}
__device__ __forceinline__ float2 upk2(ull v) {
    float2 f; asm("mov.b64 {%0,%1},%2;" : "=f"(f.x), "=f"(f.y) : "l"(v)); return f;
}
__device__ __forceinline__ ull f2fma(ull a, ull b, ull c) {
    ull d; asm("fma.rn.f32x2 %0,%1,%2,%3;" : "=l"(d) : "l"(a), "l"(b), "l"(c)); return d;
}
__device__ __forceinline__ ull f2add(ull a, ull b) {
    ull d; asm("add.rn.f32x2 %0,%1,%2;" : "=l"(d) : "l"(a), "l"(b)); return d;
}

__device__ __forceinline__ int sfun(int blk) { return (blk * 392) / 37; }  // 6272/592

// Scratch
__device__ float  g_qs2[TT*BSZ*CC];          // packed t-pairs
__device__ float  g_gate[TT*BSZ*CC];
__device__ float2 g_P[NBLK*2*TT*CC];         // interleaved (acc, macc) partials
__device__ float  g_Lp[NBLK*2*24];

// ---------------------------------------------------------------------------
// prep: q = (tok@q_w^T + q_b)*0.125 (packed t-pairs), gate = hsig(alpha)*2
// grid (8 c-chunks, 64 b), 256 threads: thread = (c_loc = tid>>3, dq = tid&7)
// one-pass, shuffle reduction over 8 dq lanes. 512 blocks -> 3.5 blocks/SM.
// ---------------------------------------------------------------------------
__global__ void __launch_bounds__(256) prep_kernel(
    const float* __restrict__ tokens,
    const float* __restrict__ q_w,  const float* __restrict__ q_b,
    const float* __restrict__ a_w,  const float* __restrict__ a_b)
{
    __shared__ float tok_t[DD*8];            // [d][t0..t5,pad,pad]
    int cq = blockIdx.x, b = blockIdx.y, tid = threadIdx.x;

    for (int i = tid; i < TT*DD; i += 256) {
        int t = i / DD, d = i % DD;
        tok_t[d*8 + t] = tokens[(t*BSZ + b)*DD + d];
    }
    __syncthreads();

    int c_loc = tid >> 3, dq = tid & 7;
    int c = cq*32 + c_loc;
    float qp[TT], ap[TT];
    #pragma unroll
    for (int t = 0; t < TT; t++) { qp[t] = 0.f; ap[t] = 0.f; }

    #pragma unroll
    for (int k = 0; k < 6; k++) {
        int d0 = k*32 + dq*4;
        float4 q4 = *reinterpret_cast<const float4*>(q_w + c*DD + d0);
        float4 a4 = *reinterpret_cast<const float4*>(a_w + c*DD + d0);
        float qv[4] = {q4.x, q4.y, q4.z, q4.w};
        float av[4] = {a4.x, a4.y, a4.z, a4.w};
        #pragma unroll
        for (int dd = 0; dd < 4; dd++) {
            float4 tA = *reinterpret_cast<const float4*>(tok_t + (d0+dd)*8);
            float4 tB = *reinterpret_cast<const float4*>(tok_t + (d0+dd)*8 + 4);
            float tv[6] = {tA.x, tA.y, tA.z, tA.w, tB.x, tB.y};
            #pragma unroll
            for (int t = 0; t < TT; t++) {
                qp[t] += qv[dd] * tv[t];
                ap[t] += av[dd] * tv[t];
            }
        }
    }
    // reduce over the 8 dq lanes
    #pragma unroll
    for (int o = 1; o < 8; o <<= 1) {
        #pragma unroll
        for (int t = 0; t < TT; t++) {
            qp[t] += __shfl_xor_sync(0xffffffffu, qp[t], o);
            ap[t] += __shfl_xor_sync(0xffffffffu, ap[t], o);
        }
    }
    if (dq == 0) {
        float qb = q_b[c], ab = a_b[c];
        #pragma unroll
        for (int t2 = 0; t2 < 3; t2++) {
            float q0 = (qp[2*t2]   + qb) * 0.125f;
            float q1 = (qp[2*t2+1] + qb) * 0.125f;
            reinterpret_cast<float2*>(g_qs2)[(t2*BSZ + b)*CC + c] = make_float2(q0, q1);
        }
        #pragma unroll
        for (int t = 0; t < TT; t++) {
            float al = ap[t] + ab + 3.0f;
            al = fminf(fmaxf(al, 0.0f), 6.0f) * (1.0f/3.0f);
            g_gate[(t*BSZ + b)*CC + c] = al;
        }
    }
}

// ---------------------------------------------------------------------------
// main: balanced persistent fused pass. 592 blocks (4/SM resident), 256 thr.
// __launch_bounds__(256,4) caps regs at 64 -> guaranteed 4 blocks/SM.
// ---------------------------------------------------------------------------
__global__ void __launch_bounds__(256, 4) main_kernel(
    const float* __restrict__ feat,
    const float* __restrict__ mlp_w,
    float* __restrict__ attn_out)
{
    extern __shared__ float sm[];
    float* fs   = sm;                        // 256*36 = 9216
    ull*   es2  = (ull*)(sm + 9216);         // 12*34 ull
    ull*   qs2  = (ull*)(sm + 10032);        // 3*256 ull
    ull*   mws2 = (ull*)(sm + 11568);        // 3*34 ull

    int blk = blockIdx.x, tid = threadIdx.x;
    int h1 = (tid >> 5) & 3, nl = tid & 31;
    int h2 = tid >> 6;
    int s = sfun(blk), e = sfun(blk + 1);

    ull acc2[3] = {0,0,0}, macc2[3] = {0,0,0}, Lacc2[3] = {0,0,0};
    int curb = -1, seg = 0;

    for (int tau = s; tau < e; tau++) {
        int b = tau / TPB;
        int n0 = (tau - b*TPB) * TN;
        bool newb = (b != curb);
        if (newb) {
            if (curb >= 0) {
                int idx = blk*2 + seg;
                float2* gp = g_P + (size_t)idx*(TT*CC);
                #pragma unroll
                for (int t2 = 0; t2 < 3; t2++) {
                    float2 ua = upk2(acc2[t2]),  um = upk2(macc2[t2]);
                    gp[(2*t2  )*CC + tid] = make_float2(ua.x, um.x);
                    gp[(2*t2+1)*CC + tid] = make_float2(ua.y, um.y);
                    acc2[t2] = 0; macc2[t2] = 0;
                }
                if (tid < 128) {
                    float lv[TT];
                    #pragma unroll
                    for (int t2 = 0; t2 < 3; t2++) {
                        float2 u = upk2(Lacc2[t2]); lv[2*t2] = u.x; lv[2*t2+1] = u.y;
                        Lacc2[t2] = 0;
                    }
                    #pragma unroll
                    for (int t = 0; t < TT; t++) {
                        #pragma unroll
                        for (int o = 16; o; o >>= 1)
                            lv[t] += __shfl_xor_sync(0xffffffffu, lv[t], o);
                    }
                    if (nl == 0) {
                        #pragma unroll
                        for (int t = 0; t < TT; t++)
                            g_Lp[idx*24 + h1*TT + t] = lv[t];
                    }
                }
                seg++;
            }
            curb = b;
        }

        __syncthreads();
        // ---- stage ----
        const float* fb = feat + (size_t)b * CC * HWN + n0;
        #pragma unroll
        for (int it = 0; it < 8; it++) {
            int c = it*32 + (tid >> 3);
            int nq = (tid & 7) * 4;
            float4 v = *reinterpret_cast<const float4*>(fb + (size_t)c*HWN + nq);
            *reinterpret_cast<float4*>(fs + c*FST + nq) = v;
        }
        if (tid < 96) {
            int t2 = tid >> 5, n = tid & 31;
            float m0 = mlp_w[(2*t2  )*HWN + n0 + n];
            float m1 = mlp_w[(2*t2+1)*HWN + n0 + n];
            mws2[t2*EST2 + n] = pk2(m0, m1);
        }
        if (newb) {
            #pragma unroll
            for (int t2 = 0; t2 < 3; t2++) {
                float2 q2 = reinterpret_cast<const float2*>(g_qs2)[(t2*BSZ + b)*CC + tid];
                qs2[t2*CC + tid] = pk2(q2.x, q2.y);
            }
        }
        __syncthreads();

        // ---- phase 1: logits + exp (warps 0..3, warp = head) ----
        if (tid < 128) {
            ull s2[3] = {0,0,0};
            const float* fsr = fs + (h1*DHH)*FST + nl;
            const ull* qb = qs2 + h1*DHH;
            #pragma unroll
            for (int d = 0; d < DHH; d += 2) {
                float f0 = fsr[d*FST];
                float f1 = fsr[d*FST + FST];
                ull ff0 = pk2(f0, f0), ff1 = pk2(f1, f1);
                #pragma unroll
                for (int t2 = 0; t2 < 3; t2++) {
                    ulonglong2 q = *reinterpret_cast<const ulonglong2*>(qb + t2*CC + d);
                    s2[t2] = f2fma(q.x, ff0, s2[t2]);
                    s2[t2] = f2fma(q.y, ff1, s2[t2]);
                }
            }
            size_t gb = ((size_t)(b*NHH + h1) * TT) * HWN + n0 + nl;
            #pragma unroll
            for (int t2 = 0; t2 < 3; t2++) {
                float2 sv = upk2(s2[t2]);
                attn_out[gb + (size_t)(2*t2  )*HWN] = sv.x;
                attn_out[gb + (size_t)(2*t2+1)*HWN] = sv.y;
                float e0 = __expf(sv.x), e1 = __expf(sv.y);   // logits O(0.3): safe
                ull ee = pk2(e0, e1);
                es2[(h1*3 + t2)*EST2 + nl] = ee;
                Lacc2[t2] = f2add(Lacc2[t2], ee);
            }
        }
        __syncthreads();

        // ---- phase 2: packed rank-1 accumulation (all 256 threads) ----
        {
            const float* fr = fs + tid*FST;
            const ull* er = es2 + (h2*3)*EST2;
            #pragma unroll
            for (int n = 0; n < TN; n += 4) {
                float4 f4 = *reinterpret_cast<const float4*>(fr + n);
                ull fa = pk2(f4.x, f4.x), fb2 = pk2(f4.y, f4.y);
                ull fc = pk2(f4.z, f4.z), fd  = pk2(f4.w, f4.w);
                #pragma unroll
                for (int t2 = 0; t2 < 3; t2++) {
                    ulonglong2 eA = *reinterpret_cast<const ulonglong2*>(er + t2*EST2 + n);
                    ulonglong2 eB = *reinterpret_cast<const ulonglong2*>(er + t2*EST2 + n + 2);
                    ulonglong2 mA = *reinterpret_cast<const ulonglong2*>(mws2 + t2*EST2 + n);
                    ulonglong2 mB = *reinterpret_cast<const ulonglong2*>(mws2 + t2*EST2 + n + 2);
                    acc2[t2]  = f2fma(eA.x, fa,  acc2[t2]);
                    acc2[t2]  = f2fma(eA.y, fb2, acc2[t2]);
                    acc2[t2]  = f2fma(eB.x, fc,  acc2[t2]);
                    acc2[t2]  = f2fma(eB.y, fd,  acc2[t2]);
                    macc2[t2] = f2fma(mA.x, fa,  macc2[t2]);
                    macc2[t2] = f2fma(mA.y, fb2, macc2[t2]);
                    macc2[t2] = f2fma(mB.x, fc,  macc2[t2]);
                    macc2[t2] = f2fma(mB.y, fd,  macc2[t2]);
                }
            }
        }
    }

    // final flush
    {
        int idx = blk*2 + seg;
        float2* gp = g_P + (size_t)idx*(TT*CC);
        #pragma unroll
        for (int t2 = 0; t2 < 3; t2++) {
            float2 ua = upk2(acc2[t2]), um = upk2(macc2[t2]);
            gp[(2*t2  )*CC + tid] = make_float2(ua.x, um.x);
            gp[(2*t2+1)*CC + tid] = make_float2(ua.y, um.y);
        }
        if (tid < 128) {
            float lv[TT];
            #pragma unroll
            for (int t2 = 0; t2 < 3; t2++) {
                float2 u = upk2(Lacc2[t2]); lv[2*t2] = u.x; lv[2*t2+1] = u.y;
            }
            #pragma unroll
            for (int t = 0; t < TT; t++) {
                #pragma unroll
                for (int o = 16; o; o >>= 1)
                    lv[t] += __shfl_xor_sync(0xffffffffu, lv[t], o);
            }
            if (nl == 0) {
                #pragma unroll
                for (int t = 0; t < TT; t++)
                    g_Lp[idx*24 + h1*TT + t] = lv[t];
            }
        }
    }
}

// ---------------------------------------------------------------------------
// epi: grid (64, 6) = (b, t). partial reduce + gate + proj + residual + LN.
// ---------------------------------------------------------------------------
__global__ void __launch_bounds__(256) epi_kernel(
    const float* __restrict__ tokens, const float* __restrict__ mlp_b,
    const float* __restrict__ proj_w, const float* __restrict__ proj_b,
    const float* __restrict__ ln_g,   const float* __restrict__ ln_b,
    float* __restrict__ out_tok)
{
    __shared__ float ts[CC];
    __shared__ float tv[DD];
    __shared__ float red[16];
    int b = blockIdx.x, t = blockIdx.y, tid = threadIdx.x;
    int w = tid >> 5, lane = tid & 31, h = tid >> 6;

    // find contributing blocks for this b
    float a = 0.f, m = 0.f, L = 0.f;
    int g = (TPB*b*37) / 392;
    while (sfun(g) > TPB*b) g--;
    while (sfun(g+1) <= TPB*b) g++;
    int lim = TPB*b + TPB;
    for (int blk = g; blk < NBLK && sfun(blk) < lim; blk++) {
        int seg = b - sfun(blk)/TPB;        // 0 or 1
        int idx = blk*2 + seg;
        float2 v = g_P[(size_t)idx*(TT*CC) + t*CC + tid];
        a += v.x; m += v.y;
        L += g_Lp[idx*24 + h*TT + t];
    }
    float v = (m + mlp_b[t] + a * (1.0f / L)) * g_gate[(t*BSZ + b)*CC + tid];
    ts[tid] = v;
    __syncthreads();

    // proj: warp w handles 24 d rows; proj_w streamed from L2
    #pragma unroll 4
    for (int dd = 0; dd < 24; dd++) {
        int d = w*24 + dd;
        const float4* prow = reinterpret_cast<const float4*>(proj_w + d*CC);
        const float4* tsr  = reinterpret_cast<const float4*>(ts);
        float4 p0 = prow[lane],      t0 = tsr[lane];
        float4 p1 = prow[lane + 32], t1 = tsr[lane + 32];
        float sum = p0.x*t0.x + p0.y*t0.y + p0.z*t0.z + p0.w*t0.w
                  + p1.x*t1.x + p1.y*t1.y + p1.z*t1.z + p1.w*t1.w;
        #pragma unroll
        for (int o = 16; o; o >>= 1) sum += __shfl_xor_sync(0xffffffffu, sum, o);
        if (lane == 0) tv[d] = sum + proj_b[d] + tokens[(t*BSZ + b)*DD + d];
    }
    __syncthreads();

    float x  = (tid < DD) ? tv[tid] : 0.0f;
    float x2 = x * x;
    #pragma unroll
    for (int o = 16; o; o >>= 1) {
        x  += __shfl_xor_sync(0xffffffffu, x,  o);
        x2 += __shfl_xor_sync(0xffffffffu, x2, o);
    }
    if (lane == 0) { red[w] = x; red[8 + w] = x2; }
    __syncthreads();
    float sA = red[0]+red[1]+red[2]+red[3]+red[4]+red[5]+red[6]+red[7];
    float sB = red[8]+red[9]+red[10]+red[11]+red[12]+red[13]+red[14]+red[15];
    float mu = sA * (1.0f/DD);
    float var = sB * (1.0f/DD) - mu*mu;
    float rstd = rsqrtf(var + 1e-5f);
    if (tid < DD) {
        out_tok[((size_t)t*BSZ + b)*DD + tid] =
            (tv[tid] - mu) * rstd * ln_g[tid] + ln_b[tid];
    }
}

// ---------------------------------------------------------------------------
extern "C" void kernel_launch(void* const* d_in, const int* in_sizes, int n_in,
                              void* d_out, int out_size)
{
    const float* feat    = (const float*)d_in[0];
    const float* tokens  = (const float*)d_in[1];
    const float* mlp_w   = (const float*)d_in[2];
    const float* mlp_b   = (const float*)d_in[3];
    const float* q_w     = (const float*)d_in[4];
    const float* q_b     = (const float*)d_in[5];
    const float* alpha_w = (const float*)d_in[6];
    const float* alpha_b = (const float*)d_in[7];
    const float* proj_w  = (const float*)d_in[8];
    const float* proj_b  = (const float*)d_in[9];
    const float* ln_g    = (const float*)d_in[10];
    const float* ln_b    = (const float*)d_in[11];

    float* out      = (float*)d_out;
    float* out_tok  = out;                      // [T, bs, D]
    float* out_attn = out + (size_t)TT*BSZ*DD;  // [bs, h, T, HW]

    size_t smB = 11772 * sizeof(float);   // 47088 B

    prep_kernel<<<dim3(8, BSZ), 256>>>(tokens, q_w, q_b, alpha_w, alpha_b);
    main_kernel<<<NBLK, 256, smB>>>(feat, mlp_w, out_attn);
    epi_kernel<<<dim3(BSZ, TT), 256>>>(tokens, mlp_b, proj_w, proj_b,
                                       ln_g, ln_b, out_tok);
}

// round 4
// speedup vs baseline: 1.7513x; 1.2801x over previous
#include <cuda_runtime.h>
#include <cuda_bf16.h>

#define BSZ   64
#define CC    256
#define HWN   3136
#define TT    6
#define NHH   4
#define DHH   64
#define DD    192
#define NBLK  592         // 148 SMs * 4 resident blocks: one persistent wave
#define TPB   98          // n-tiles per batch (TN=32)
#define TN    32
#define EST2  34          // es2/mws2 row stride (ull units)

typedef unsigned long long ull;

__device__ __forceinline__ ull pk2(float lo, float hi) {
    ull r; asm("mov.b64 %0,{%1,%2};" : "=l"(r) : "f"(lo), "f"(hi)); return r;
}
__device__ __forceinline__ float2 upk2(ull v) {
    float2 f; asm("mov.b64 {%0,%1},%2;" : "=f"(f.x), "=f"(f.y) : "l"(v)); return f;
}
__device__ __forceinline__ ull f2fma(ull a, ull b, ull c) {
    ull d; asm("fma.rn.f32x2 %0,%1,%2,%3;" : "=l"(d) : "l"(a), "l"(b), "l"(c)); return d;
}
__device__ __forceinline__ ull f2add(ull a, ull b) {
    ull d; asm("add.rn.f32x2 %0,%1,%2;" : "=l"(d) : "l"(a), "l"(b)); return d;
}

__device__ __forceinline__ int sfun(int blk) { return (blk * 392) / 37; }  // 6272/592

// Scratch
__device__ float  g_qs2[TT*BSZ*CC];          // packed t-pairs
__device__ float  g_gate[TT*BSZ*CC];
__device__ float2 g_P[NBLK*2*TT*CC];         // interleaved (acc, macc) partials
__device__ float  g_Lp[NBLK*2*24];

// ---------------------------------------------------------------------------
// prep: q = (tok@q_w^T + q_b)*0.125 (packed t-pairs), gate = hsig(alpha)*2
// grid (8 c-chunks, 64 b). tok_t stride 9 -> dq lanes on distinct banks.
// ---------------------------------------------------------------------------
__global__ void __launch_bounds__(256) prep_kernel(
    const float* __restrict__ tokens,
    const float* __restrict__ q_w,  const float* __restrict__ q_b,
    const float* __restrict__ a_w,  const float* __restrict__ a_b)
{
    __shared__ float tok_t[DD*9];
    int cq = blockIdx.x, b = blockIdx.y, tid = threadIdx.x;

    for (int i = tid; i < TT*DD; i += 256) {
        int t = i / DD, d = i % DD;
        tok_t[d*9 + t] = tokens[(t*BSZ + b)*DD + d];
    }
    __syncthreads();

    int c_loc = tid >> 3, dq = tid & 7;
    int c = cq*32 + c_loc;
    float qp[TT], ap[TT];
    #pragma unroll
    for (int t = 0; t < TT; t++) { qp[t] = 0.f; ap[t] = 0.f; }

    #pragma unroll
    for (int k = 0; k < 6; k++) {
        int d0 = k*32 + dq*4;
        float4 q4 = *reinterpret_cast<const float4*>(q_w + c*DD + d0);
        float4 a4 = *reinterpret_cast<const float4*>(a_w + c*DD + d0);
        float qv[4] = {q4.x, q4.y, q4.z, q4.w};
        float av[4] = {a4.x, a4.y, a4.z, a4.w};
        #pragma unroll
        for (int dd = 0; dd < 4; dd++) {
            const float* tr = tok_t + (d0 + dd)*9;
            #pragma unroll
            for (int t = 0; t < TT; t++) {
                float tv = tr[t];
                qp[t] += qv[dd] * tv;
                ap[t] += av[dd] * tv;
            }
        }
    }
    #pragma unroll
    for (int o = 1; o < 8; o <<= 1) {
        #pragma unroll
        for (int t = 0; t < TT; t++) {
            qp[t] += __shfl_xor_sync(0xffffffffu, qp[t], o);
            ap[t] += __shfl_xor_sync(0xffffffffu, ap[t], o);
        }
    }
    if (dq == 0) {
        float qb = q_b[c], ab = a_b[c];
        #pragma unroll
        for (int t2 = 0; t2 < 3; t2++) {
            float q0 = (qp[2*t2]   + qb) * 0.125f;
            float q1 = (qp[2*t2+1] + qb) * 0.125f;
            reinterpret_cast<float2*>(g_qs2)[(t2*BSZ + b)*CC + c] = make_float2(q0, q1);
        }
        #pragma unroll
        for (int t = 0; t < TT; t++) {
            float al = ap[t] + ab + 3.0f;
            al = fminf(fmaxf(al, 0.0f), 6.0f) * (1.0f/3.0f);
            g_gate[(t*BSZ + b)*CC + c] = al;
        }
    }
}

// ---------------------------------------------------------------------------
// main: persistent fused pass, 592 blocks (4/SM), 256 threads.
// fs: XOR-swizzled 16B chunks, 128B rows (all accesses at wavefront floor).
// warps 0-3: logits+exp (head = warp). warps 4-7: rank-1 accum, 2 rows/thread.
// ---------------------------------------------------------------------------
__global__ void __launch_bounds__(256, 4) main_kernel(
    const float* __restrict__ feat,
    const float* __restrict__ mlp_w,
    float* __restrict__ attn_out)
{
    extern __shared__ float sm[];
    float* fs   = sm;                        // 256*32 = 8192 floats (32KB)
    ull*   es2  = (ull*)(sm + 8192);         // 12 rows * 34 ull
    ull*   qs2  = (ull*)(sm + 9008);         // 3*256 ull
    ull*   mws2 = (ull*)(sm + 10544);        // 3*34 ull

    int blk = blockIdx.x, tid = threadIdx.x;
    int wid = tid >> 5, lane = tid & 31;
    int s = sfun(blk), e = sfun(blk + 1);

    // phase-1 ids (warps 0..3)
    int h1 = wid & 3, nlh = (lane >> 2) << 2, nll = lane & 3;
    // phase-2 ids (warps 4..7): rows rA = h*64+lane, rB = rA+32
    int hp = wid - 4;
    int rA = hp*DHH + lane;
    int sx = (lane & 7) << 2;

    ull accA[3] = {0,0,0}, maccA[3] = {0,0,0};
    ull accB[3] = {0,0,0}, maccB[3] = {0,0,0};
    ull Lacc2[3] = {0,0,0};
    int curb = -1, seg = 0;

    for (int tau = s; tau < e; tau++) {
        int b = tau / TPB;
        int n0 = (tau - b*TPB) * TN;
        bool newb = (b != curb);
        if (newb) {
            if (curb >= 0) {
                int idx = blk*2 + seg;
                if (wid >= 4) {
                    float2* gp = g_P + (size_t)idx*(TT*CC);
                    #pragma unroll
                    for (int t2 = 0; t2 < 3; t2++) {
                        float2 uaA = upk2(accA[t2]), umA = upk2(maccA[t2]);
                        float2 uaB = upk2(accB[t2]), umB = upk2(maccB[t2]);
                        gp[(2*t2  )*CC + rA     ] = make_float2(uaA.x, umA.x);
                        gp[(2*t2+1)*CC + rA     ] = make_float2(uaA.y, umA.y);
                        gp[(2*t2  )*CC + rA + 32] = make_float2(uaB.x, umB.x);
                        gp[(2*t2+1)*CC + rA + 32] = make_float2(uaB.y, umB.y);
                        accA[t2]=0; maccA[t2]=0; accB[t2]=0; maccB[t2]=0;
                    }
                } else {
                    float lv[TT];
                    #pragma unroll
                    for (int t2 = 0; t2 < 3; t2++) {
                        float2 u = upk2(Lacc2[t2]); lv[2*t2] = u.x; lv[2*t2+1] = u.y;
                        Lacc2[t2] = 0;
                    }
                    #pragma unroll
                    for (int t = 0; t < TT; t++) {
                        #pragma unroll
                        for (int o = 16; o; o >>= 1)
                            lv[t] += __shfl_xor_sync(0xffffffffu, lv[t], o);
                    }
                    if (lane == 0) {
                        #pragma unroll
                        for (int t = 0; t < TT; t++)
                            g_Lp[idx*24 + h1*TT + t] = lv[t];
                    }
                }
                seg++;
            }
            curb = b;
        }

        __syncthreads();
        // ---- stage (all threads): swizzled STS.128 ----
        const float* fb = feat + (size_t)b * CC * HWN + n0;
        {
            int q4o = (tid & 7) << 2;                // global chunk offset (floats)
            #pragma unroll
            for (int it = 0; it < 8; it++) {
                int r = it*32 + (tid >> 3);
                float4 v = *reinterpret_cast<const float4*>(fb + (size_t)r*HWN + q4o);
                *reinterpret_cast<float4*>(fs + r*32 + (q4o ^ ((r & 7) << 2))) = v;
            }
        }
        if (tid < 96) {
            int t2 = tid >> 5, n = tid & 31;
            float m0 = mlp_w[(2*t2  )*HWN + n0 + n];
            float m1 = mlp_w[(2*t2+1)*HWN + n0 + n];
            mws2[t2*EST2 + n] = pk2(m0, m1);
        }
        if (newb) {
            #pragma unroll
            for (int t2 = 0; t2 < 3; t2++) {
                float2 q2 = reinterpret_cast<const float2*>(g_qs2)[(t2*BSZ + b)*CC + tid];
                qs2[t2*CC + tid] = pk2(q2.x, q2.y);
            }
        }
        __syncthreads();

        if (wid < 4) {
            // ---- phase 1: logits + exp ----
            ull s2[3] = {0,0,0};
            const float* fsr = fs + (h1*DHH)*32;
            const ull* qb = qs2 + h1*DHH;
            #pragma unroll
            for (int d = 0; d < DHH; d += 2) {
                float f0 = fsr[ d   *32 + ((nlh ^ (( d   &7)<<2)) | nll)];
                float f1 = fsr[(d+1)*32 + ((nlh ^ (((d+1)&7)<<2)) | nll)];
                ull ff0 = pk2(f0, f0), ff1 = pk2(f1, f1);
                #pragma unroll
                for (int t2 = 0; t2 < 3; t2++) {
                    ulonglong2 q = *reinterpret_cast<const ulonglong2*>(qb + t2*CC + d);
                    s2[t2] = f2fma(q.x, ff0, s2[t2]);
                    s2[t2] = f2fma(q.y, ff1, s2[t2]);
                }
            }
            size_t gb = ((size_t)(b*NHH + h1) * TT) * HWN + n0 + lane;
            #pragma unroll
            for (int t2 = 0; t2 < 3; t2++) {
                float2 sv = upk2(s2[t2]);
                attn_out[gb + (size_t)(2*t2  )*HWN] = sv.x;
                attn_out[gb + (size_t)(2*t2+1)*HWN] = sv.y;
                float e0 = __expf(sv.x), e1 = __expf(sv.y);   // logits O(0.3): safe
                ull ee = pk2(e0, e1);
                es2[(h1*3 + t2)*EST2 + lane] = ee;
                Lacc2[t2] = f2add(Lacc2[t2], ee);
            }
        }
        __syncthreads();

        if (wid >= 4) {
            // ---- phase 2: 2 rows (rA, rA+32), e/m broadcasts amortized ----
            const float* frA = fs + rA*32;
            const float* frB = frA + 32*32;
            const ull* er = es2 + (hp*3)*EST2;
            #pragma unroll
            for (int q = 0; q < 8; q++) {
                int sw = ((q << 2) ^ sx);
                float4 fA = *reinterpret_cast<const float4*>(frA + sw);
                float4 fB = *reinterpret_cast<const float4*>(frB + sw);
                ull a0 = pk2(fA.x, fA.x), a1 = pk2(fA.y, fA.y);
                ull a2 = pk2(fA.z, fA.z), a3 = pk2(fA.w, fA.w);
                ull b0 = pk2(fB.x, fB.x), b1 = pk2(fB.y, fB.y);
                ull b2 = pk2(fB.z, fB.z), b3 = pk2(fB.w, fB.w);
                int n = q << 2;
                #pragma unroll
                for (int t2 = 0; t2 < 3; t2++) {
                    ulonglong2 eA = *reinterpret_cast<const ulonglong2*>(er + t2*EST2 + n);
                    ulonglong2 eB = *reinterpret_cast<const ulonglong2*>(er + t2*EST2 + n + 2);
                    ulonglong2 mA = *reinterpret_cast<const ulonglong2*>(mws2 + t2*EST2 + n);
                    ulonglong2 mB = *reinterpret_cast<const ulonglong2*>(mws2 + t2*EST2 + n + 2);
                    accA[t2]  = f2fma(eA.x, a0, accA[t2]);
                    accA[t2]  = f2fma(eA.y, a1, accA[t2]);
                    accA[t2]  = f2fma(eB.x, a2, accA[t2]);
                    accA[t2]  = f2fma(eB.y, a3, accA[t2]);
                    accB[t2]  = f2fma(eA.x, b0, accB[t2]);
                    accB[t2]  = f2fma(eA.y, b1, accB[t2]);
                    accB[t2]  = f2fma(eB.x, b2, accB[t2]);
                    accB[t2]  = f2fma(eB.y, b3, accB[t2]);
                    maccA[t2] = f2fma(mA.x, a0, maccA[t2]);
                    maccA[t2] = f2fma(mA.y, a1, maccA[t2]);
                    maccA[t2] = f2fma(mB.x, a2, maccA[t2]);
                    maccA[t2] = f2fma(mB.y, a3, maccA[t2]);
                    maccB[t2] = f2fma(mA.x, b0, maccB[t2]);
                    maccB[t2] = f2fma(mA.y, b1, maccB[t2]);
                    maccB[t2] = f2fma(mB.x, b2, maccB[t2]);
                    maccB[t2] = f2fma(mB.y, b3, maccB[t2]);
                }
            }
        }
    }

    // final flush
    {
        int idx = blk*2 + seg;
        if (wid >= 4) {
            float2* gp = g_P + (size_t)idx*(TT*CC);
            #pragma unroll
            for (int t2 = 0; t2 < 3; t2++) {
                float2 uaA = upk2(accA[t2]), umA = upk2(maccA[t2]);
                float2 uaB = upk2(accB[t2]), umB = upk2(maccB[t2]);
                gp[(2*t2  )*CC + rA     ] = make_float2(uaA.x, umA.x);
                gp[(2*t2+1)*CC + rA     ] = make_float2(uaA.y, umA.y);
                gp[(2*t2  )*CC + rA + 32] = make_float2(uaB.x, umB.x);
                gp[(2*t2+1)*CC + rA + 32] = make_float2(uaB.y, umB.y);
            }
        } else {
            float lv[TT];
            #pragma unroll
            for (int t2 = 0; t2 < 3; t2++) {
                float2 u = upk2(Lacc2[t2]); lv[2*t2] = u.x; lv[2*t2+1] = u.y;
            }
            #pragma unroll
            for (int t = 0; t < TT; t++) {
                #pragma unroll
                for (int o = 16; o; o >>= 1)
                    lv[t] += __shfl_xor_sync(0xffffffffu, lv[t], o);
            }
            if (lane == 0) {
                #pragma unroll
                for (int t = 0; t < TT; t++)
                    g_Lp[idx*24 + h1*TT + t] = lv[t];
            }
        }
    }
}

// ---------------------------------------------------------------------------
// epi: grid (64, 6) = (b, t). partial reduce + gate + proj + residual + LN.
// ---------------------------------------------------------------------------
__global__ void __launch_bounds__(256) epi_kernel(
    const float* __restrict__ tokens, const float* __restrict__ mlp_b,
    const float* __restrict__ proj_w, const float* __restrict__ proj_b,
    const float* __restrict__ ln_g,   const float* __restrict__ ln_b,
    float* __restrict__ out_tok)
{
    __shared__ float ts[CC];
    __shared__ float tv[DD];
    __shared__ float red[16];
    int b = blockIdx.x, t = blockIdx.y, tid = threadIdx.x;
    int w = tid >> 5, lane = tid & 31, h = tid >> 6;

    float a = 0.f, m = 0.f, L = 0.f;
    int g = (TPB*b*37) / 392;
    while (sfun(g) > TPB*b) g--;
    while (sfun(g+1) <= TPB*b) g++;
    int lim = TPB*b + TPB;
    for (int blk = g; blk < NBLK && sfun(blk) < lim; blk++) {
        int seg = b - sfun(blk)/TPB;        // 0 or 1
        int idx = blk*2 + seg;
        float2 v = g_P[(size_t)idx*(TT*CC) + t*CC + tid];
        a += v.x; m += v.y;
        L += g_Lp[idx*24 + h*TT + t];
    }
    float v = (m + mlp_b[t] + a * (1.0f / L)) * g_gate[(t*BSZ + b)*CC + tid];
    ts[tid] = v;
    __syncthreads();

    #pragma unroll 4
    for (int dd = 0; dd < 24; dd++) {
        int d = w*24 + dd;
        const float4* prow = reinterpret_cast<const float4*>(proj_w + d*CC);
        const float4* tsr  = reinterpret_cast<const float4*>(ts);
        float4 p0 = prow[lane],      t0 = tsr[lane];
        float4 p1 = prow[lane + 32], t1 = tsr[lane + 32];
        float sum = p0.x*t0.x + p0.y*t0.y + p0.z*t0.z + p0.w*t0.w
                  + p1.x*t1.x + p1.y*t1.y + p1.z*t1.z + p1.w*t1.w;
        #pragma unroll
        for (int o = 16; o; o >>= 1) sum += __shfl_xor_sync(0xffffffffu, sum, o);
        if (lane == 0) tv[d] = sum + proj_b[d] + tokens[(t*BSZ + b)*DD + d];
    }
    __syncthreads();

    float x  = (tid < DD) ? tv[tid] : 0.0f;
    float x2 = x * x;
    #pragma unroll
    for (int o = 16; o; o >>= 1) {
        x  += __shfl_xor_sync(0xffffffffu, x,  o);
        x2 += __shfl_xor_sync(0xffffffffu, x2, o);
    }
    if (lane == 0) { red[w] = x; red[8 + w] = x2; }
    __syncthreads();
    float sA = red[0]+red[1]+red[2]+red[3]+red[4]+red[5]+red[6]+red[7];
    float sB = red[8]+red[9]+red[10]+red[11]+red[12]+red[13]+red[14]+red[15];
    float mu = sA * (1.0f/DD);
    float var = sB * (1.0f/DD) - mu*mu;
    float rstd = rsqrtf(var + 1e-5f);
    if (tid < DD) {
        out_tok[((size_t)t*BSZ + b)*DD + tid] =
            (tv[tid] - mu) * rstd * ln_g[tid] + ln_b[tid];
    }
}

// ---------------------------------------------------------------------------
extern "C" void kernel_launch(void* const* d_in, const int* in_sizes, int n_in,
                              void* d_out, int out_size)
{
    const float* feat    = (const float*)d_in[0];
    const float* tokens  = (const float*)d_in[1];
    const float* mlp_w   = (const float*)d_in[2];
    const float* mlp_b   = (const float*)d_in[3];
    const float* q_w     = (const float*)d_in[4];
    const float* q_b     = (const float*)d_in[5];
    const float* alpha_w = (const float*)d_in[6];
    const float* alpha_b = (const float*)d_in[7];
    const float* proj_w  = (const float*)d_in[8];
    const float* proj_b  = (const float*)d_in[9];
    const float* ln_g    = (const float*)d_in[10];
    const float* ln_b    = (const float*)d_in[11];

    float* out      = (float*)d_out;
    float* out_tok  = out;                      // [T, bs, D]
    float* out_attn = out + (size_t)TT*BSZ*DD;  // [bs, h, T, HW]

    size_t smB = 10748 * sizeof(float);   // 42992 B

    cudaFuncSetAttribute(main_kernel, cudaFuncAttributeMaxDynamicSharedMemorySize, (int)smB);

    prep_kernel<<<dim3(8, BSZ), 256>>>(tokens, q_w, q_b, alpha_w, alpha_b);
    main_kernel<<<NBLK, 256, smB>>>(feat, mlp_w, out_attn);
    epi_kernel<<<dim3(BSZ, TT), 256>>>(tokens, mlp_b, proj_w, proj_b,
                                       ln_g, ln_b, out_tok);
}